// round 14
// baseline (speedup 1.0000x reference)
#include <cuda_runtime.h>
#include <math.h>

#define NCOMP 20000
#define NMEAS 64
#define SDIM 6
#define MDIM 3
#define NPART 128
#define LOG2PI 1.8378770664093453f
#define PD_C 0.98f
#define CLUTTER_C 1e-4f

#define ENS_OFF 0
#define W_OFF   (NMEAS * NCOMP * SDIM)
#define COV_OFF (W_OFF + NMEAS * NCOMP)

// ---------------- device scratch ----------------
__device__ float  g_part[NPART * 27];
__device__ int    g_ctr = 0;
__device__ float  g_P[36];
__device__ float  g_terms[NMEAS * NCOMP];

// ---------------- shared device helper: linearization core ---------------
__device__ __forceinline__ void lin_core(
    const float* __restrict__ Ps, const float* __restrict__ Rs,
    float x, float y, float z,
    float& yb0, float& yb1, float& yb2,
    float H[3][3], float K[6][3],
    float& i00, float& i01, float& i02,
    float& i11, float& i12, float& i22, float& logdet) {
    float rxy2 = x * x + y * y;
    float rho2 = rxy2 + z * z;
    float rho  = sqrtf(rho2);
    float rxy  = sqrtf(rxy2);

    yb0 = rho;
    yb1 = atan2f(y, x);
    yb2 = asinf(z / rho);

    float irho = 1.0f / rho;
    H[0][0] = x * irho; H[0][1] = y * irho; H[0][2] = z * irho;
    float irxy2 = 1.0f / rxy2;
    H[1][0] = -y * irxy2; H[1][1] = x * irxy2; H[1][2] = 0.0f;
    float den = 1.0f / (rho2 * rxy);
    H[2][0] = -x * z * den; H[2][1] = -y * z * den; H[2][2] = rxy / rho2;

    float PHt[6][3];
#pragma unroll
    for (int i = 0; i < 6; i++)
#pragma unroll
        for (int k = 0; k < 3; k++)
            PHt[i][k] = Ps[i * 6 + 0] * H[k][0] + Ps[i * 6 + 1] * H[k][1] +
                        Ps[i * 6 + 2] * H[k][2];

    float Sf[3][3];
#pragma unroll
    for (int k = 0; k < 3; k++)
#pragma unroll
        for (int l = 0; l < 3; l++)
            Sf[k][l] = H[k][0] * PHt[0][l] + H[k][1] * PHt[1][l] +
                       H[k][2] * PHt[2][l] + Rs[k * 3 + l];

    float s00 = Sf[0][0], s11 = Sf[1][1], s22 = Sf[2][2];
    float s01 = 0.5f * (Sf[0][1] + Sf[1][0]);
    float s02 = 0.5f * (Sf[0][2] + Sf[2][0]);
    float s12 = 0.5f * (Sf[1][2] + Sf[2][1]);
    float q0 = rsqrtf(s00), q1 = rsqrtf(s11), q2 = rsqrtf(s22);
    float m01 = s01 * q0 * q1;
    float m02 = s02 * q0 * q2;
    float m12 = s12 * q1 * q2;

    float c00 = 1.0f - m12 * m12;
    float c01 = m02 * m12 - m01;
    float c02 = m01 * m12 - m02;
    float detM = c00 + m01 * c01 + m02 * c02;
    float idetM = 1.0f / detM;
    i00 = c00 * idetM * q0 * q0;
    i01 = c01 * idetM * q0 * q1;
    i02 = c02 * idetM * q0 * q2;
    i11 = (1.0f - m02 * m02) * idetM * q1 * q1;
    i12 = (m01 * m02 - m12) * idetM * q1 * q2;
    i22 = (1.0f - m01 * m01) * idetM * q2 * q2;
    logdet = logf(detM * s00 * s11 * s22);

#pragma unroll
    for (int i = 0; i < 6; i++) {
        K[i][0] = PHt[i][0] * i00 + PHt[i][1] * i01 + PHt[i][2] * i02;
        K[i][1] = PHt[i][0] * i01 + PHt[i][1] * i11 + PHt[i][2] * i12;
        K[i][2] = PHt[i][0] * i02 + PHt[i][1] * i12 + PHt[i][2] * i22;
    }
}

// ---------------- kernel 1: fused anchored covariance + finalize ----------
__global__ void k_cov(const float* __restrict__ means) {
    float a[6];
#pragma unroll
    for (int i = 0; i < 6; i++) a[i] = __ldg(&means[i]);

    float v[27];
#pragma unroll
    for (int k = 0; k < 27; k++) v[k] = 0.0f;

    for (int r = blockIdx.x * blockDim.x + threadIdx.x; r < NCOMP;
         r += gridDim.x * blockDim.x) {
        float d[6];
#pragma unroll
        for (int i = 0; i < 6; i++) d[i] = means[r * 6 + i] - a[i];
#pragma unroll
        for (int i = 0; i < 6; i++) v[i] += d[i];
        int idx = 6;
#pragma unroll
        for (int i = 0; i < 6; i++)
#pragma unroll
            for (int j = i; j < 6; j++)
                v[idx++] = fmaf(d[i], d[j], v[idx]);
    }

    int lane = threadIdx.x & 31;
    int warp = threadIdx.x >> 5;
    __shared__ float sh[8][27];
#pragma unroll
    for (int k = 0; k < 27; k++) {
        float s = v[k];
#pragma unroll
        for (int off = 16; off > 0; off >>= 1)
            s += __shfl_down_sync(0xffffffffu, s, off);
        if (lane == 0) sh[warp][k] = s;
    }
    __syncthreads();
    if (threadIdx.x < 27) {
        float s = 0.0f;
#pragma unroll
        for (int w = 0; w < 8; w++) s += sh[w][threadIdx.x];
        g_part[blockIdx.x * 27 + threadIdx.x] = s;
    }
    __syncthreads();
    __threadfence();

    __shared__ int s_last;
    if (threadIdx.x == 0) {
        int c = atomicAdd(&g_ctr, 1);
        s_last = (c == NPART - 1);
    }
    __syncthreads();
    if (!s_last) return;
    __threadfence();

    __shared__ double acc[27];
    int t = threadIdx.x;
    if (t < 27) {
        double s = 0.0;
        for (int b = 0; b < NPART; b++) s += (double)g_part[b * 27 + t];
        acc[t] = s;
    }
    __syncthreads();
    if (t < 36) {
        int i = t / 6, j = t % 6;
        double mdi = acc[i] / (double)NCOMP;
        double mdj = acc[j] / (double)NCOMP;
        int ii = (i < j) ? i : j;
        int jj = (i < j) ? j : i;
        int tri = 6 + (ii * (13 - ii)) / 2 + (jj - ii);
        double c = (acc[tri] - (double)NCOMP * mdi * mdj) / (double)(NCOMP - 1);
        double bw = pow(4.0 / ((double)NCOMP * (SDIM + 2)), 2.0 / (SDIM + 4));
        double d = (double)(i - j);
        double loc = exp(-(d * d) / (2.0 * 3.0 * 3.0));
        g_P[i * 6 + j] = (float)(bw * c * loc);
    }
    if (t == 0) g_ctr = 0;
}

// ---------------- kernel 2: ensemble + terms -------------------------------
#define MSPLIT 8
#define MCH (NMEAS / MSPLIT)    // 8
__global__ void __launch_bounds__(256)
k_ens(const float* __restrict__ means,
      const float* __restrict__ wts,
      const float* __restrict__ Rm,
      const float* __restrict__ meas,
      const int* __restrict__ mask,
      float* __restrict__ out) {
    __shared__ float Ps[36];
    __shared__ float Rs[9];
    __shared__ float zm[MCH * 3];
    __shared__ int mk[MCH];
    int tid = threadIdx.x;
    int m0 = blockIdx.y * MCH;
    if (tid < 36) Ps[tid] = g_P[tid];
    if (tid < 9)  Rs[tid] = Rm[tid];
    if (tid < MCH * 3) zm[tid] = meas[m0 * 3 + tid];
    if (tid < MCH)     mk[tid] = mask[m0 + tid];
    __syncthreads();

    int n = blockIdx.x * blockDim.x + tid;
    if (n >= NCOMP) return;

    float mu[6];
#pragma unroll
    for (int i = 0; i < 6; i++) mu[i] = means[n * 6 + i];

    float yb0, yb1, yb2, H[3][3], K[6][3];
    float i00, i01, i02, i11, i12, i22, logdet;
    lin_core(Ps, Rs, mu[0], mu[1], mu[2], yb0, yb1, yb2, H, K,
             i00, i01, i02, i11, i12, i22, logdet);

    float c0 = logf(PD_C) + logf(wts[n]) - 0.5f * (logdet + 3.0f * LOG2PI);

#pragma unroll
    for (int mm = 0; mm < MCH; mm++) {
        int m = m0 + mm;
        float r0 = yb0 - zm[mm * 3 + 0];
        float r1 = yb1 - zm[mm * 3 + 1];
        float r2 = yb2 - zm[mm * 3 + 2];
        float maha = i00 * r0 * r0 + i11 * r1 * r1 + i22 * r2 * r2 +
                     2.0f * (i01 * r0 * r1 + i02 * r0 * r2 + i12 * r1 * r2);
        g_terms[m * NCOMP + n] = c0 - 0.5f * maha;

        bool on = (mk[mm] != 0);
        float p0 = 0.f, p1 = 0.f, p2 = 0.f, p3 = 0.f, p4 = 0.f, p5 = 0.f;
        if (on) {
            p0 = mu[0] - (K[0][0] * r0 + K[0][1] * r1 + K[0][2] * r2);
            p1 = mu[1] - (K[1][0] * r0 + K[1][1] * r1 + K[1][2] * r2);
            p2 = mu[2] - (K[2][0] * r0 + K[2][1] * r1 + K[2][2] * r2);
            p3 = mu[3] - (K[3][0] * r0 + K[3][1] * r1 + K[3][2] * r2);
            p4 = mu[4] - (K[4][0] * r0 + K[4][1] * r1 + K[4][2] * r2);
            p5 = mu[5] - (K[5][0] * r0 + K[5][1] * r1 + K[5][2] * r2);
        }
        float2* dst = reinterpret_cast<float2*>(out + ENS_OFF +
                                                (size_t)(m * NCOMP + n) * 6);
        __stcs(&dst[0], make_float2(p0, p1));
        __stcs(&dst[1], make_float2(p2, p3));
        __stcs(&dst[2], make_float2(p4, p5));
    }
}

// ---------------- kernel 3: fused logsumexp + weights ----------------
__global__ void k_lse_weights(const int* __restrict__ mask,
                              float* __restrict__ out) {
    int m = blockIdx.x;
    int tid = threadIdx.x;
    int lane = tid & 31, warp = tid >> 5;
    __shared__ float sh[32];
    __shared__ float s_logden;

    const float* terms = g_terms + m * NCOMP;

    float mx = -3.4e38f;
    for (int n = tid; n < NCOMP; n += 1024)
        mx = fmaxf(mx, terms[n]);
#pragma unroll
    for (int off = 16; off > 0; off >>= 1)
        mx = fmaxf(mx, __shfl_down_sync(0xffffffffu, mx, off));
    if (lane == 0) sh[warp] = mx;
    __syncthreads();
    if (warp == 0) {
        float v = sh[lane];
#pragma unroll
        for (int off = 16; off > 0; off >>= 1)
            v = fmaxf(v, __shfl_down_sync(0xffffffffu, v, off));
        if (lane == 0) sh[0] = v;
    }
    __syncthreads();
    float bm = sh[0];
    __syncthreads();

    float sum = 0.0f;
    for (int n = tid; n < NCOMP; n += 1024)
        sum += __expf(terms[n] - bm);
#pragma unroll
    for (int off = 16; off > 0; off >>= 1)
        sum += __shfl_down_sync(0xffffffffu, sum, off);
    if (lane == 0) sh[warp] = sum;
    __syncthreads();
    if (warp == 0) {
        float v = sh[lane];
#pragma unroll
        for (int off = 16; off > 0; off >>= 1)
            v += __shfl_down_sync(0xffffffffu, v, off);
        if (lane == 0) {
            float lse = bm + logf(v);
            float a = logf(CLUTTER_C);
            float hi = fmaxf(a, lse), lo = fminf(a, lse);
            s_logden = hi + log1pf(expf(lo - hi));
        }
    }
    __syncthreads();

    float ld = s_logden;
    bool on = (mask[m] != 0);
    float* wout = out + W_OFF + m * NCOMP;
    for (int n = tid; n < NCOMP; n += 1024) {
        float w = on ? __expf(terms[n] - ld) : 0.0f;
        __stcs(wout + n, w);
    }
}

// ---------------- kernel 4: fused post_cov compute + broadcast ------------
// One thread per (component n, float4-quad q). Recomputes the linearization
// (9x redundancy per n — trivial fp32) so no post_cov table or extra kernel
// is needed; the 184 MB broadcast starts right after k_cov.
#define MGRP 8
#define MGROUPS (NMEAS / MGRP)   // 8
__global__ void __launch_bounds__(256)
k_covbcast(const float* __restrict__ means,
           const float* __restrict__ Rm,
           const int* __restrict__ mask,
           float* __restrict__ out) {
    __shared__ float Ps[36];
    __shared__ float Rs[9];
    __shared__ int mk[MGRP];
    int tid = threadIdx.x;
    int m0 = blockIdx.y * MGRP;
    if (tid < 36) Ps[tid] = g_P[tid];
    if (tid < 9)  Rs[tid] = Rm[tid];
    if (tid < MGRP) mk[tid] = mask[m0 + tid];
    __syncthreads();

    int idx = blockIdx.x * blockDim.x + tid;
    if (idx >= NCOMP * 9) return;
    int n = idx / 9;
    int q = idx - n * 9;          // which float4 of the 36 floats

    float x = __ldg(&means[n * 6 + 0]);
    float y = __ldg(&means[n * 6 + 1]);
    float z = __ldg(&means[n * 6 + 2]);

    float yb0, yb1, yb2, H[3][3], K[6][3];
    float i00, i01, i02, i11, i12, i22, logdet;
    lin_core(Ps, Rs, x, y, z, yb0, yb1, yb2, H, K,
             i00, i01, i02, i11, i12, i22, logdet);

    // this thread's 4 linear entries p = 4q .. 4q+3 of post_cov (row-major 6x6)
    float vv[4];
#pragma unroll
    for (int e = 0; e < 4; e++) {
        int p = 4 * q + e;
        int i = p / 6, j = p - i * 6;
        float kh0 = K[i][0] * H[0][0] + K[i][1] * H[1][0] + K[i][2] * H[2][0];
        float kh1 = K[i][0] * H[0][1] + K[i][1] * H[1][1] + K[i][2] * H[2][1];
        float kh2 = K[i][0] * H[0][2] + K[i][1] * H[1][2] + K[i][2] * H[2][2];
        vv[e] = Ps[i * 6 + j] -
                (kh0 * Ps[0 * 6 + j] + kh1 * Ps[1 * 6 + j] + kh2 * Ps[2 * 6 + j]);
    }
    float4 v = make_float4(vv[0], vv[1], vv[2], vv[3]);
    const float4 zz = make_float4(0.f, 0.f, 0.f, 0.f);

    float4* dst = reinterpret_cast<float4*>(out + COV_OFF);
#pragma unroll
    for (int k = 0; k < MGRP; k++) {
        int m = m0 + k;
        float4 w = (mk[k] != 0) ? v : zz;
        __stcs(&dst[(size_t)m * (NCOMP * 9) + idx], w);
    }
}

// ---------------- launch ----------------
static cudaStream_t g_s2 = nullptr;
static cudaEvent_t  g_evFork = nullptr, g_evJoin = nullptr;

extern "C" void kernel_launch(void* const* d_in, const int* in_sizes, int n_in,
                              void* d_out, int out_size) {
    const float* means = (const float*)d_in[0];
    const float* wts   = (const float*)d_in[1];
    const float* meas  = (const float*)d_in[2];
    const float* Rm    = (const float*)d_in[3];
    const int*   mask  = (const int*)d_in[4];
    float* out = (float*)d_out;

    if (g_s2 == nullptr) {
        cudaStreamCreateWithFlags(&g_s2, cudaStreamNonBlocking);
        cudaEventCreateWithFlags(&g_evFork, cudaEventDisableTiming);
        cudaEventCreateWithFlags(&g_evJoin, cudaEventDisableTiming);
    }

    // prolog: covariance only
    k_cov<<<NPART, 256>>>(means);

    // fork the 184 MB broadcast immediately after P is ready
    cudaEventRecord(g_evFork, 0);
    cudaStreamWaitEvent(g_s2, g_evFork, 0);
    dim3 gc((NCOMP * 9 + 255) / 256, MGROUPS);
    k_covbcast<<<gc, 256, 0, g_s2>>>(means, Rm, mask, out);
    cudaEventRecord(g_evJoin, g_s2);

    // main stream: ensemble+terms, then logsumexp+weights — concurrent
    dim3 gu((NCOMP + 255) / 256, MSPLIT);
    k_ens<<<gu, 256>>>(means, wts, Rm, meas, mask, out);
    k_lse_weights<<<NMEAS, 1024>>>(mask, out);

    cudaStreamWaitEvent(0, g_evJoin, 0);
}

// round 15
// speedup vs baseline: 1.1486x; 1.1486x over previous
#include <cuda_runtime.h>
#include <math.h>

#define NCOMP 20000
#define NMEAS 64
#define SDIM 6
#define MDIM 3
#define NPART 128
#define LOG2PI 1.8378770664093453f
#define PD_C 0.98f
#define CLUTTER_C 1e-4f

#define ENS_OFF 0
#define W_OFF   (NMEAS * NCOMP * SDIM)
#define COV_OFF (W_OFF + NMEAS * NCOMP)

// ---------------- device scratch ----------------
__device__ float  g_part[NPART * 27];
__device__ int    g_ctr = 0;
__device__ float  g_P[36];
__device__ float4 g_postcov4[NCOMP * 9];
__device__ float  g_terms[NMEAS * NCOMP];

// ---------------- kernel 1: fused anchored covariance + finalize ----------
__global__ void k_cov(const float* __restrict__ means) {
    float a[6];
#pragma unroll
    for (int i = 0; i < 6; i++) a[i] = __ldg(&means[i]);

    float v[27];
#pragma unroll
    for (int k = 0; k < 27; k++) v[k] = 0.0f;

    for (int r = blockIdx.x * blockDim.x + threadIdx.x; r < NCOMP;
         r += gridDim.x * blockDim.x) {
        float d[6];
#pragma unroll
        for (int i = 0; i < 6; i++) d[i] = means[r * 6 + i] - a[i];
#pragma unroll
        for (int i = 0; i < 6; i++) v[i] += d[i];
        int idx = 6;
#pragma unroll
        for (int i = 0; i < 6; i++)
#pragma unroll
            for (int j = i; j < 6; j++)
                v[idx++] = fmaf(d[i], d[j], v[idx]);
    }

    int lane = threadIdx.x & 31;
    int warp = threadIdx.x >> 5;
    __shared__ float sh[8][27];
#pragma unroll
    for (int k = 0; k < 27; k++) {
        float s = v[k];
#pragma unroll
        for (int off = 16; off > 0; off >>= 1)
            s += __shfl_down_sync(0xffffffffu, s, off);
        if (lane == 0) sh[warp][k] = s;
    }
    __syncthreads();
    if (threadIdx.x < 27) {
        float s = 0.0f;
#pragma unroll
        for (int w = 0; w < 8; w++) s += sh[w][threadIdx.x];
        g_part[blockIdx.x * 27 + threadIdx.x] = s;
    }
    __syncthreads();
    __threadfence();

    __shared__ int s_last;
    if (threadIdx.x == 0) {
        int c = atomicAdd(&g_ctr, 1);
        s_last = (c == NPART - 1);
    }
    __syncthreads();
    if (!s_last) return;
    __threadfence();

    __shared__ double acc[27];
    int t = threadIdx.x;
    if (t < 27) {
        double s = 0.0;
        for (int b = 0; b < NPART; b++) s += (double)g_part[b * 27 + t];
        acc[t] = s;
    }
    __syncthreads();
    if (t < 36) {
        int i = t / 6, j = t % 6;
        double mdi = acc[i] / (double)NCOMP;
        double mdj = acc[j] / (double)NCOMP;
        int ii = (i < j) ? i : j;
        int jj = (i < j) ? j : i;
        int tri = 6 + (ii * (13 - ii)) / 2 + (jj - ii);
        double c = (acc[tri] - (double)NCOMP * mdi * mdj) / (double)(NCOMP - 1);
        double bw = pow(4.0 / ((double)NCOMP * (SDIM + 2)), 2.0 / (SDIM + 4));
        double d = (double)(i - j);
        double loc = exp(-(d * d) / (2.0 * 3.0 * 3.0));
        g_P[i * 6 + j] = (float)(bw * c * loc);
    }
    if (t == 0) g_ctr = 0;
}

// ---------------- kernel 2: fused linearization + per-measurement update --
__global__ void __launch_bounds__(128)
k_pern_update(const float* __restrict__ means,
              const float* __restrict__ wts,
              const float* __restrict__ Rm,
              const float* __restrict__ meas,
              const int* __restrict__ mask,
              float* __restrict__ out) {
    __shared__ float Ps[36];
    __shared__ float Rs[9];
    __shared__ float zm[NMEAS * 3];
    __shared__ int mk[NMEAS];
    int tid = threadIdx.x;
    if (tid < 36) Ps[tid] = g_P[tid];
    if (tid < 9)  Rs[tid] = Rm[tid];
    for (int i = tid; i < NMEAS * 3; i += 128) zm[i] = meas[i];
    if (tid < NMEAS) mk[tid] = mask[tid];
    __syncthreads();

    int n = blockIdx.x * blockDim.x + tid;
    if (n >= NCOMP) return;

    float mu[6];
#pragma unroll
    for (int i = 0; i < 6; i++) mu[i] = means[n * 6 + i];
    float x = mu[0], y = mu[1], z = mu[2];

    float rxy2 = x * x + y * y;
    float rho2 = rxy2 + z * z;
    float rho  = sqrtf(rho2);
    float rxy  = sqrtf(rxy2);

    float yb0 = rho;
    float yb1 = atan2f(y, x);
    float yb2 = asinf(z / rho);

    float H[3][3];
    float irho = 1.0f / rho;
    H[0][0] = x * irho; H[0][1] = y * irho; H[0][2] = z * irho;
    float irxy2 = 1.0f / rxy2;
    H[1][0] = -y * irxy2; H[1][1] = x * irxy2; H[1][2] = 0.0f;
    float den = 1.0f / (rho2 * rxy);
    H[2][0] = -x * z * den; H[2][1] = -y * z * den; H[2][2] = rxy / rho2;

    float PHt[6][3];
#pragma unroll
    for (int i = 0; i < 6; i++)
#pragma unroll
        for (int k = 0; k < 3; k++)
            PHt[i][k] = Ps[i * 6 + 0] * H[k][0] + Ps[i * 6 + 1] * H[k][1] +
                        Ps[i * 6 + 2] * H[k][2];

    float Sf[3][3];
#pragma unroll
    for (int k = 0; k < 3; k++)
#pragma unroll
        for (int l = 0; l < 3; l++)
            Sf[k][l] = H[k][0] * PHt[0][l] + H[k][1] * PHt[1][l] +
                       H[k][2] * PHt[2][l] + Rs[k * 3 + l];

    float s00 = Sf[0][0], s11 = Sf[1][1], s22 = Sf[2][2];
    float s01 = 0.5f * (Sf[0][1] + Sf[1][0]);
    float s02 = 0.5f * (Sf[0][2] + Sf[2][0]);
    float s12 = 0.5f * (Sf[1][2] + Sf[2][1]);
    float q0 = rsqrtf(s00), q1 = rsqrtf(s11), q2 = rsqrtf(s22);
    float m01 = s01 * q0 * q1;
    float m02 = s02 * q0 * q2;
    float m12 = s12 * q1 * q2;

    float c00 = 1.0f - m12 * m12;
    float c01 = m02 * m12 - m01;
    float c02 = m01 * m12 - m02;
    float detM = c00 + m01 * c01 + m02 * c02;
    float idetM = 1.0f / detM;
    float i00 = c00 * idetM * q0 * q0;
    float i01 = c01 * idetM * q0 * q1;
    float i02 = c02 * idetM * q0 * q2;
    float i11 = (1.0f - m02 * m02) * idetM * q1 * q1;
    float i12 = (m01 * m02 - m12) * idetM * q1 * q2;
    float i22 = (1.0f - m01 * m01) * idetM * q2 * q2;
    float logdet = logf(detM * s00 * s11 * s22);

    float K[6][3];
#pragma unroll
    for (int i = 0; i < 6; i++) {
        K[i][0] = PHt[i][0] * i00 + PHt[i][1] * i01 + PHt[i][2] * i02;
        K[i][1] = PHt[i][0] * i01 + PHt[i][1] * i11 + PHt[i][2] * i12;
        K[i][2] = PHt[i][0] * i02 + PHt[i][1] * i12 + PHt[i][2] * i22;
    }

    float KH[6][3];
#pragma unroll
    for (int i = 0; i < 6; i++)
#pragma unroll
        for (int j = 0; j < 3; j++)
            KH[i][j] = K[i][0] * H[0][j] + K[i][1] * H[1][j] + K[i][2] * H[2][j];

    float* pc = reinterpret_cast<float*>(g_postcov4);
#pragma unroll
    for (int i = 0; i < 6; i++)
#pragma unroll
        for (int j = 0; j < 6; j++) {
            float v = Ps[i * 6 + j] -
                      (KH[i][0] * Ps[0 * 6 + j] + KH[i][1] * Ps[1 * 6 + j] +
                       KH[i][2] * Ps[2 * 6 + j]);
            pc[n * 36 + i * 6 + j] = v;
        }

    float c0 = logf(PD_C) + logf(wts[n]) - 0.5f * (logdet + 3.0f * LOG2PI);

#pragma unroll 4
    for (int m = 0; m < NMEAS; m++) {
        float r0 = yb0 - zm[m * 3 + 0];
        float r1 = yb1 - zm[m * 3 + 1];
        float r2 = yb2 - zm[m * 3 + 2];
        float maha = i00 * r0 * r0 + i11 * r1 * r1 + i22 * r2 * r2 +
                     2.0f * (i01 * r0 * r1 + i02 * r0 * r2 + i12 * r1 * r2);
        g_terms[m * NCOMP + n] = c0 - 0.5f * maha;

        bool on = (mk[m] != 0);
        float p0 = 0.f, p1 = 0.f, p2 = 0.f, p3 = 0.f, p4 = 0.f, p5 = 0.f;
        if (on) {
            p0 = mu[0] - (K[0][0] * r0 + K[0][1] * r1 + K[0][2] * r2);
            p1 = mu[1] - (K[1][0] * r0 + K[1][1] * r1 + K[1][2] * r2);
            p2 = mu[2] - (K[2][0] * r0 + K[2][1] * r1 + K[2][2] * r2);
            p3 = mu[3] - (K[3][0] * r0 + K[3][1] * r1 + K[3][2] * r2);
            p4 = mu[4] - (K[4][0] * r0 + K[4][1] * r1 + K[4][2] * r2);
            p5 = mu[5] - (K[5][0] * r0 + K[5][1] * r1 + K[5][2] * r2);
        }
        float2* dst = reinterpret_cast<float2*>(out + ENS_OFF +
                                                (size_t)(m * NCOMP + n) * 6);
        __stcs(&dst[0], make_float2(p0, p1));
        __stcs(&dst[1], make_float2(p2, p3));
        __stcs(&dst[2], make_float2(p4, p5));
    }
}

// ---------------- kernel 3: fused logsumexp + weights ----------------
__global__ void k_lse_weights(const int* __restrict__ mask,
                              float* __restrict__ out) {
    int m = blockIdx.x;
    int tid = threadIdx.x;
    int lane = tid & 31, warp = tid >> 5;
    __shared__ float sh[32];
    __shared__ float s_logden;

    const float* terms = g_terms + m * NCOMP;

    float mx = -3.4e38f;
    for (int n = tid; n < NCOMP; n += 1024)
        mx = fmaxf(mx, terms[n]);
#pragma unroll
    for (int off = 16; off > 0; off >>= 1)
        mx = fmaxf(mx, __shfl_down_sync(0xffffffffu, mx, off));
    if (lane == 0) sh[warp] = mx;
    __syncthreads();
    if (warp == 0) {
        float v = sh[lane];
#pragma unroll
        for (int off = 16; off > 0; off >>= 1)
            v = fmaxf(v, __shfl_down_sync(0xffffffffu, v, off));
        if (lane == 0) sh[0] = v;
    }
    __syncthreads();
    float bm = sh[0];
    __syncthreads();

    float sum = 0.0f;
    for (int n = tid; n < NCOMP; n += 1024)
        sum += expf(terms[n] - bm);
#pragma unroll
    for (int off = 16; off > 0; off >>= 1)
        sum += __shfl_down_sync(0xffffffffu, sum, off);
    if (lane == 0) sh[warp] = sum;
    __syncthreads();
    if (warp == 0) {
        float v = sh[lane];
#pragma unroll
        for (int off = 16; off > 0; off >>= 1)
            v += __shfl_down_sync(0xffffffffu, v, off);
        if (lane == 0) {
            float lse = bm + logf(v);
            float a = logf(CLUTTER_C);
            float hi = fmaxf(a, lse), lo = fminf(a, lse);
            s_logden = hi + log1pf(expf(lo - hi));
        }
    }
    __syncthreads();

    float ld = s_logden;
    bool on = (mask[m] != 0);
    float* wout = out + W_OFF + m * NCOMP;
    for (int n = tid; n < NCOMP; n += 1024) {
        float w = on ? expf(terms[n] - ld) : 0.0f;
        __stcs(wout + n, w);
    }
}

// ---------------- kernel 4: covariance broadcast (MGRP=16) ----------------
#define MGRP 16
#define MGROUPS (NMEAS / MGRP)   // 4
__global__ void k_covbcast(const int* __restrict__ mask,
                           float* __restrict__ out) {
    __shared__ int mk[MGRP];
    int m0 = blockIdx.y * MGRP;
    if (threadIdx.x < MGRP) mk[threadIdx.x] = mask[m0 + threadIdx.x];
    __syncthreads();

    int idx = blockIdx.x * blockDim.x + threadIdx.x;
    if (idx >= NCOMP * 9) return;

    float4 v = __ldg(&g_postcov4[idx]);
    const float4 z = make_float4(0.f, 0.f, 0.f, 0.f);
    float4* dst = reinterpret_cast<float4*>(out + COV_OFF);
#pragma unroll
    for (int k = 0; k < MGRP; k++) {
        int m = m0 + k;
        float4 w = (mk[k] != 0) ? v : z;
        __stcs(&dst[(size_t)m * (NCOMP * 9) + idx], w);
    }
}

// ---------------- launch: fork covbcast onto a side stream ----------------
static cudaStream_t g_s2 = nullptr;
static cudaEvent_t  g_evFork = nullptr, g_evJoin = nullptr;

extern "C" void kernel_launch(void* const* d_in, const int* in_sizes, int n_in,
                              void* d_out, int out_size) {
    const float* means = (const float*)d_in[0];
    const float* wts   = (const float*)d_in[1];
    const float* meas  = (const float*)d_in[2];
    const float* Rm    = (const float*)d_in[3];
    const int*   mask  = (const int*)d_in[4];
    float* out = (float*)d_out;

    if (g_s2 == nullptr) {
        cudaStreamCreateWithFlags(&g_s2, cudaStreamNonBlocking);
        cudaEventCreateWithFlags(&g_evFork, cudaEventDisableTiming);
        cudaEventCreateWithFlags(&g_evJoin, cudaEventDisableTiming);
    }

    k_cov<<<NPART, 256>>>(means);
    k_pern_update<<<(NCOMP + 127) / 128, 128>>>(means, wts, Rm, meas, mask, out);

    cudaEventRecord(g_evFork, 0);
    cudaStreamWaitEvent(g_s2, g_evFork, 0);
    dim3 gc((NCOMP * 9 + 255) / 256, MGROUPS);
    k_covbcast<<<gc, 256, 0, g_s2>>>(mask, out);
    cudaEventRecord(g_evJoin, g_s2);

    k_lse_weights<<<NMEAS, 1024>>>(mask, out);

    cudaStreamWaitEvent(0, g_evJoin, 0);
}

// round 16
// speedup vs baseline: 1.2486x; 1.0870x over previous
#include <cuda_runtime.h>
#include <math.h>

#define NCOMP 20000
#define NMEAS 64
#define SDIM 6
#define MDIM 3
#define NPART 64
#define LOG2PI 1.8378770664093453f
#define PD_C 0.98f
#define CLUTTER_C 1e-4f

#define ENS_OFF 0
#define W_OFF   (NMEAS * NCOMP * SDIM)
#define COV_OFF (W_OFF + NMEAS * NCOMP)

// ---------------- device scratch ----------------
__device__ float  g_part[NPART * 27];
__device__ int    g_ctr = 0;
__device__ float  g_P[36];
__device__ float4 g_postcov4[NCOMP * 9];
__device__ float  g_terms[NMEAS * NCOMP];

// ---------------- kernel 1: fused anchored covariance + finalize ----------
__global__ void k_cov(const float* __restrict__ means) {
    float a[6];
#pragma unroll
    for (int i = 0; i < 6; i++) a[i] = __ldg(&means[i]);

    float v[27];
#pragma unroll
    for (int k = 0; k < 27; k++) v[k] = 0.0f;

    for (int r = blockIdx.x * blockDim.x + threadIdx.x; r < NCOMP;
         r += gridDim.x * blockDim.x) {
        float d[6];
#pragma unroll
        for (int i = 0; i < 6; i++) d[i] = means[r * 6 + i] - a[i];
#pragma unroll
        for (int i = 0; i < 6; i++) v[i] += d[i];
        int idx = 6;
#pragma unroll
        for (int i = 0; i < 6; i++)
#pragma unroll
            for (int j = i; j < 6; j++)
                v[idx++] = fmaf(d[i], d[j], v[idx]);
    }

    int lane = threadIdx.x & 31;
    int warp = threadIdx.x >> 5;
    __shared__ float sh[8][27];
#pragma unroll
    for (int k = 0; k < 27; k++) {
        float s = v[k];
#pragma unroll
        for (int off = 16; off > 0; off >>= 1)
            s += __shfl_down_sync(0xffffffffu, s, off);
        if (lane == 0) sh[warp][k] = s;
    }
    __syncthreads();
    if (threadIdx.x < 27) {
        float s = 0.0f;
#pragma unroll
        for (int w = 0; w < 8; w++) s += sh[w][threadIdx.x];
        g_part[blockIdx.x * 27 + threadIdx.x] = s;
    }
    __syncthreads();
    __threadfence();

    __shared__ int s_last;
    if (threadIdx.x == 0) {
        int c = atomicAdd(&g_ctr, 1);
        s_last = (c == NPART - 1);
    }
    __syncthreads();
    if (!s_last) return;
    __threadfence();

    __shared__ double acc[27];
    int t = threadIdx.x;
    if (t < 27) {
        double s = 0.0;
        for (int b = 0; b < NPART; b++) s += (double)g_part[b * 27 + t];
        acc[t] = s;
    }
    __syncthreads();
    if (t < 36) {
        int i = t / 6, j = t % 6;
        double mdi = acc[i] / (double)NCOMP;
        double mdj = acc[j] / (double)NCOMP;
        int ii = (i < j) ? i : j;
        int jj = (i < j) ? j : i;
        int tri = 6 + (ii * (13 - ii)) / 2 + (jj - ii);
        double c = (acc[tri] - (double)NCOMP * mdi * mdj) / (double)(NCOMP - 1);
        double bw = pow(4.0 / ((double)NCOMP * (SDIM + 2)), 2.0 / (SDIM + 4));
        double d = (double)(i - j);
        double loc = exp(-(d * d) / (2.0 * 3.0 * 3.0));
        g_P[i * 6 + j] = (float)(bw * c * loc);
    }
    if (t == 0) g_ctr = 0;
}

// ---------------- kernel 2: fused linearization + per-measurement update --
__global__ void __launch_bounds__(128)
k_pern_update(const float* __restrict__ means,
              const float* __restrict__ wts,
              const float* __restrict__ Rm,
              const float* __restrict__ meas,
              const int* __restrict__ mask,
              float* __restrict__ out) {
    __shared__ float Ps[36];
    __shared__ float Rs[9];
    __shared__ float zm[NMEAS * 3];
    __shared__ int mk[NMEAS];
    int tid = threadIdx.x;
    if (tid < 36) Ps[tid] = g_P[tid];
    if (tid < 9)  Rs[tid] = Rm[tid];
    for (int i = tid; i < NMEAS * 3; i += 128) zm[i] = meas[i];
    if (tid < NMEAS) mk[tid] = mask[tid];
    __syncthreads();

    int n = blockIdx.x * blockDim.x + tid;
    if (n >= NCOMP) return;

    float mu[6];
#pragma unroll
    for (int i = 0; i < 6; i++) mu[i] = means[n * 6 + i];
    float x = mu[0], y = mu[1], z = mu[2];

    float rxy2 = x * x + y * y;
    float rho2 = rxy2 + z * z;
    float rho  = sqrtf(rho2);
    float rxy  = sqrtf(rxy2);

    float yb0 = rho;
    float yb1 = atan2f(y, x);
    float yb2 = asinf(z / rho);

    float H[3][3];
    float irho = 1.0f / rho;
    H[0][0] = x * irho; H[0][1] = y * irho; H[0][2] = z * irho;
    float irxy2 = 1.0f / rxy2;
    H[1][0] = -y * irxy2; H[1][1] = x * irxy2; H[1][2] = 0.0f;
    float den = 1.0f / (rho2 * rxy);
    H[2][0] = -x * z * den; H[2][1] = -y * z * den; H[2][2] = rxy / rho2;

    float PHt[6][3];
#pragma unroll
    for (int i = 0; i < 6; i++)
#pragma unroll
        for (int k = 0; k < 3; k++)
            PHt[i][k] = Ps[i * 6 + 0] * H[k][0] + Ps[i * 6 + 1] * H[k][1] +
                        Ps[i * 6 + 2] * H[k][2];

    float Sf[3][3];
#pragma unroll
    for (int k = 0; k < 3; k++)
#pragma unroll
        for (int l = 0; l < 3; l++)
            Sf[k][l] = H[k][0] * PHt[0][l] + H[k][1] * PHt[1][l] +
                       H[k][2] * PHt[2][l] + Rs[k * 3 + l];

    float s00 = Sf[0][0], s11 = Sf[1][1], s22 = Sf[2][2];
    float s01 = 0.5f * (Sf[0][1] + Sf[1][0]);
    float s02 = 0.5f * (Sf[0][2] + Sf[2][0]);
    float s12 = 0.5f * (Sf[1][2] + Sf[2][1]);
    float q0 = rsqrtf(s00), q1 = rsqrtf(s11), q2 = rsqrtf(s22);
    float m01 = s01 * q0 * q1;
    float m02 = s02 * q0 * q2;
    float m12 = s12 * q1 * q2;

    float c00 = 1.0f - m12 * m12;
    float c01 = m02 * m12 - m01;
    float c02 = m01 * m12 - m02;
    float detM = c00 + m01 * c01 + m02 * c02;
    float idetM = 1.0f / detM;
    float i00 = c00 * idetM * q0 * q0;
    float i01 = c01 * idetM * q0 * q1;
    float i02 = c02 * idetM * q0 * q2;
    float i11 = (1.0f - m02 * m02) * idetM * q1 * q1;
    float i12 = (m01 * m02 - m12) * idetM * q1 * q2;
    float i22 = (1.0f - m01 * m01) * idetM * q2 * q2;
    float logdet = logf(detM * s00 * s11 * s22);

    float K[6][3];
#pragma unroll
    for (int i = 0; i < 6; i++) {
        K[i][0] = PHt[i][0] * i00 + PHt[i][1] * i01 + PHt[i][2] * i02;
        K[i][1] = PHt[i][0] * i01 + PHt[i][1] * i11 + PHt[i][2] * i12;
        K[i][2] = PHt[i][0] * i02 + PHt[i][1] * i12 + PHt[i][2] * i22;
    }

    float KH[6][3];
#pragma unroll
    for (int i = 0; i < 6; i++)
#pragma unroll
        for (int j = 0; j < 3; j++)
            KH[i][j] = K[i][0] * H[0][j] + K[i][1] * H[1][j] + K[i][2] * H[2][j];

    float* pc = reinterpret_cast<float*>(g_postcov4);
#pragma unroll
    for (int i = 0; i < 6; i++)
#pragma unroll
        for (int j = 0; j < 6; j++) {
            float v = Ps[i * 6 + j] -
                      (KH[i][0] * Ps[0 * 6 + j] + KH[i][1] * Ps[1 * 6 + j] +
                       KH[i][2] * Ps[2 * 6 + j]);
            pc[n * 36 + i * 6 + j] = v;
        }

    float c0 = logf(PD_C) + logf(wts[n]) - 0.5f * (logdet + 3.0f * LOG2PI);

#pragma unroll 4
    for (int m = 0; m < NMEAS; m++) {
        float r0 = yb0 - zm[m * 3 + 0];
        float r1 = yb1 - zm[m * 3 + 1];
        float r2 = yb2 - zm[m * 3 + 2];
        float maha = i00 * r0 * r0 + i11 * r1 * r1 + i22 * r2 * r2 +
                     2.0f * (i01 * r0 * r1 + i02 * r0 * r2 + i12 * r1 * r2);
        g_terms[m * NCOMP + n] = c0 - 0.5f * maha;

        bool on = (mk[m] != 0);
        float p0 = 0.f, p1 = 0.f, p2 = 0.f, p3 = 0.f, p4 = 0.f, p5 = 0.f;
        if (on) {
            p0 = mu[0] - (K[0][0] * r0 + K[0][1] * r1 + K[0][2] * r2);
            p1 = mu[1] - (K[1][0] * r0 + K[1][1] * r1 + K[1][2] * r2);
            p2 = mu[2] - (K[2][0] * r0 + K[2][1] * r1 + K[2][2] * r2);
            p3 = mu[3] - (K[3][0] * r0 + K[3][1] * r1 + K[3][2] * r2);
            p4 = mu[4] - (K[4][0] * r0 + K[4][1] * r1 + K[4][2] * r2);
            p5 = mu[5] - (K[5][0] * r0 + K[5][1] * r1 + K[5][2] * r2);
        }
        float2* dst = reinterpret_cast<float2*>(out + ENS_OFF +
                                                (size_t)(m * NCOMP + n) * 6);
        __stcs(&dst[0], make_float2(p0, p1));
        __stcs(&dst[1], make_float2(p2, p3));
        __stcs(&dst[2], make_float2(p4, p5));
    }
}

// ---------------- kernel 3: fused logsumexp + weights ----------------
__global__ void k_lse_weights(const int* __restrict__ mask,
                              float* __restrict__ out) {
    int m = blockIdx.x;
    int tid = threadIdx.x;
    int lane = tid & 31, warp = tid >> 5;
    __shared__ float sh[32];
    __shared__ float s_logden;

    const float* terms = g_terms + m * NCOMP;

    float mx = -3.4e38f;
    for (int n = tid; n < NCOMP; n += 1024)
        mx = fmaxf(mx, terms[n]);
#pragma unroll
    for (int off = 16; off > 0; off >>= 1)
        mx = fmaxf(mx, __shfl_down_sync(0xffffffffu, mx, off));
    if (lane == 0) sh[warp] = mx;
    __syncthreads();
    if (warp == 0) {
        float v = sh[lane];
#pragma unroll
        for (int off = 16; off > 0; off >>= 1)
            v = fmaxf(v, __shfl_down_sync(0xffffffffu, v, off));
        if (lane == 0) sh[0] = v;
    }
    __syncthreads();
    float bm = sh[0];
    __syncthreads();

    float sum = 0.0f;
    for (int n = tid; n < NCOMP; n += 1024)
        sum += __expf(terms[n] - bm);
#pragma unroll
    for (int off = 16; off > 0; off >>= 1)
        sum += __shfl_down_sync(0xffffffffu, sum, off);
    if (lane == 0) sh[warp] = sum;
    __syncthreads();
    if (warp == 0) {
        float v = sh[lane];
#pragma unroll
        for (int off = 16; off > 0; off >>= 1)
            v += __shfl_down_sync(0xffffffffu, v, off);
        if (lane == 0) {
            float lse = bm + logf(v);
            float a = logf(CLUTTER_C);
            float hi = fmaxf(a, lse), lo = fminf(a, lse);
            s_logden = hi + log1pf(expf(lo - hi));
        }
    }
    __syncthreads();

    float ld = s_logden;
    bool on = (mask[m] != 0);
    float* wout = out + W_OFF + m * NCOMP;
    for (int n = tid; n < NCOMP; n += 1024) {
        float w = on ? __expf(terms[n] - ld) : 0.0f;
        __stcs(wout + n, w);
    }
}

// ---------------- kernel 4: covariance broadcast (MGRP=8, champion) -------
#define MGRP 8
#define MGROUPS (NMEAS / MGRP)   // 8
__global__ void k_covbcast(const int* __restrict__ mask,
                           float* __restrict__ out) {
    __shared__ int mk[MGRP];
    int m0 = blockIdx.y * MGRP;
    if (threadIdx.x < MGRP) mk[threadIdx.x] = mask[m0 + threadIdx.x];
    __syncthreads();

    int idx = blockIdx.x * blockDim.x + threadIdx.x;
    if (idx >= NCOMP * 9) return;

    float4 v = __ldg(&g_postcov4[idx]);
    const float4 z = make_float4(0.f, 0.f, 0.f, 0.f);
    float4* dst = reinterpret_cast<float4*>(out + COV_OFF);
#pragma unroll
    for (int k = 0; k < MGRP; k++) {
        int m = m0 + k;
        float4 w = (mk[k] != 0) ? v : z;
        __stcs(&dst[(size_t)m * (NCOMP * 9) + idx], w);
    }
}

// ---------------- launch: fork covbcast onto a side stream ----------------
static cudaStream_t g_s2 = nullptr;
static cudaEvent_t  g_evFork = nullptr, g_evJoin = nullptr;

extern "C" void kernel_launch(void* const* d_in, const int* in_sizes, int n_in,
                              void* d_out, int out_size) {
    const float* means = (const float*)d_in[0];
    const float* wts   = (const float*)d_in[1];
    const float* meas  = (const float*)d_in[2];
    const float* Rm    = (const float*)d_in[3];
    const int*   mask  = (const int*)d_in[4];
    float* out = (float*)d_out;

    if (g_s2 == nullptr) {
        cudaStreamCreateWithFlags(&g_s2, cudaStreamNonBlocking);
        cudaEventCreateWithFlags(&g_evFork, cudaEventDisableTiming);
        cudaEventCreateWithFlags(&g_evJoin, cudaEventDisableTiming);
    }

    k_cov<<<NPART, 256>>>(means);
    k_pern_update<<<(NCOMP + 127) / 128, 128>>>(means, wts, Rm, meas, mask, out);

    cudaEventRecord(g_evFork, 0);
    cudaStreamWaitEvent(g_s2, g_evFork, 0);
    dim3 gc((NCOMP * 9 + 255) / 256, MGROUPS);
    k_covbcast<<<gc, 256, 0, g_s2>>>(mask, out);
    cudaEventRecord(g_evJoin, g_s2);

    k_lse_weights<<<NMEAS, 1024>>>(mask, out);

    cudaStreamWaitEvent(0, g_evJoin, 0);
}